// round 17
// baseline (speedup 1.0000x reference)
#include <cuda_runtime.h>
#include <cuda_bf16.h>
#include <cstdint>

#define N_NODES   100000
#define N_EDGES   1600000
#define N_WEIGHTS 256
#define D         16
#define SC_THREADS 512
#define SC_ITER   8
#define SC_CHUNK  (SC_THREADS * SC_ITER)   // 4096 edges per scatter block
#define NSPLIT    4                         // counter/segment split factor
#define BIN_CAP   8192
#define SEG_CAP   (BIN_CAP / NSPLIT)        // 2048 slots per segment
#define ACC_N4    (N_NODES * D / 4)         // 400,000 float4s

// ---------------- scratch (persistent across graph replays) ----------------
__device__ int   g_bin_fill[NSPLIT * N_WEIGHTS]; // [parity][bin] counts; zeroed by relu_k
__device__ int2  g_suv[N_WEIGHTS * BIN_CAP];
__device__ float g_acc[N_NODES * D];             // zeroed by scatter_k each call

// ---------------- helpers ----------------
__device__ __forceinline__ unsigned long long pack2(float lo, float hi) {
    unsigned long long r;
    asm("mov.b64 %0, {%1, %2};" : "=l"(r) : "f"(lo), "f"(hi));
    return r;
}
__device__ __forceinline__ void fma2(unsigned long long& d,
                                     unsigned long long a, unsigned long long b) {
    asm("fma.rn.f32x2 %0, %1, %2, %0;" : "+l"(d) : "l"(a), "l"(b));
}
__device__ __forceinline__ void unpack2(unsigned long long v, float& lo, float& hi) {
    asm("mov.b64 {%0, %1}, %2;" : "=f"(lo), "=f"(hi) : "l"(v));
}
__device__ __forceinline__ void red_add_v4(float* p, float a, float b, float c, float d) {
    asm volatile("red.global.add.v4.f32 [%0], {%1, %2, %3, %4};"
                 :: "l"(p), "f"(a), "f"(b), "f"(c), "f"(d) : "memory");
}

// ---------------- kernels ----------------

// One-pass counting-sort scatter into bump-allocated QUARTER-BIN segments.
// blockIdx.x & 3 selects the bin's counter/region quarter, cutting
// per-address global-atomic serialization 4x vs a single counter.
__global__ void __launch_bounds__(SC_THREADS)
scatter_k(const int* __restrict__ u, const int* __restrict__ v,
          const int* __restrict__ widx, int E) {
    __shared__ int  cnt[N_WEIGHTS];
    __shared__ int  lstart[N_WEIGHTS];
    __shared__ int  gbase[N_WEIGHTS];
    __shared__ int  wsum[8];
    __shared__ int2 sval[SC_CHUNK];
    __shared__ unsigned char sbin2[SC_CHUNK];

    const int tid  = threadIdx.x;
    const int lane = tid & 31;
    const int wrp  = tid >> 5;
    const int par  = blockIdx.x & (NSPLIT - 1);
    const int blk0 = blockIdx.x * SC_CHUNK;
    if (blk0 >= E) return;
    const int n = min(SC_CHUNK, E - blk0);

    // zero accumulator slice (2 float4 per thread; rides in stall shadow)
    {
        int z = blockIdx.x * (2 * SC_THREADS) + tid;
        if (z < ACC_N4) ((float4*)g_acc)[z] = make_float4(0.f, 0.f, 0.f, 0.f);
        z += SC_THREADS;
        if (z < ACC_N4) ((float4*)g_acc)[z] = make_float4(0.f, 0.f, 0.f, 0.f);
    }

    if (tid < N_WEIGHTS) cnt[tid] = 0;
    __syncthreads();

    const int e0 = blk0 + tid * SC_ITER;
    const bool act = (e0 < E);   // E % 8 == 0

    int eu[SC_ITER], ev[SC_ITER], ew[SC_ITER], er[SC_ITER];
    if (act) {
        const int4* u4 = (const int4*)(u + e0);
        const int4* v4 = (const int4*)(v + e0);
        const int4* w4 = (const int4*)(widx + e0);
        int4 ua = u4[0], ub = u4[1];
        int4 va = v4[0], vb = v4[1];
        int4 wa = w4[0], wb = w4[1];
        eu[0]=ua.x; eu[1]=ua.y; eu[2]=ua.z; eu[3]=ua.w;
        eu[4]=ub.x; eu[5]=ub.y; eu[6]=ub.z; eu[7]=ub.w;
        ev[0]=va.x; ev[1]=va.y; ev[2]=va.z; ev[3]=va.w;
        ev[4]=vb.x; ev[5]=vb.y; ev[6]=vb.z; ev[7]=vb.w;
        ew[0]=wa.x; ew[1]=wa.y; ew[2]=wa.z; ew[3]=wa.w;
        ew[4]=wb.x; ew[5]=wb.y; ew[6]=wb.z; ew[7]=wb.w;
#pragma unroll
        for (int i = 0; i < SC_ITER; i++)
            er[i] = atomicAdd(&cnt[ew[i]], 1);
    }
    __syncthreads();

    // global bump-alloc issued EARLY (latency hidden under the scan)
    int c = 0, s = 0, gb = 0;
    if (tid < N_WEIGHTS) {
        c = cnt[tid];
        gb = c ? atomicAdd(&g_bin_fill[par * N_WEIGHTS + tid], c) : 0;
        s = c;
#pragma unroll
        for (int off = 1; off < 32; off <<= 1) {
            int t = __shfl_up_sync(0xffffffffu, s, off);
            if (lane >= off) s += t;
        }
        if (lane == 31) wsum[wrp] = s;
    }
    __syncthreads();
    if (wrp == 0 && lane < 8) {
        int t = wsum[lane];
#pragma unroll
        for (int off = 1; off < 8; off <<= 1) {
            int q = __shfl_up_sync(0xffu, t, off);
            if (lane >= off) t += q;
        }
        wsum[lane] = t;
    }
    __syncthreads();
    if (tid < N_WEIGHTS) {
        int incl = s + (wrp ? wsum[wrp - 1] : 0);
        lstart[tid] = incl - c;
        gbase[tid]  = tid * BIN_CAP + par * SEG_CAP + gb;
    }
    __syncthreads();

    if (act) {
#pragma unroll
        for (int i = 0; i < SC_ITER; i++) {
            int b = ew[i];
            int slot = lstart[b] + er[i];
            sval[slot]  = make_int2(eu[i], ev[i]);
            sbin2[slot] = (unsigned char)b;
        }
    }
    __syncthreads();

    for (int sIdx = tid; sIdx < n; sIdx += SC_THREADS) {
        int b = sbin2[sIdx];
        g_suv[gbase[b] + (sIdx - lstart[b])] = sval[sIdx];
    }
}

// Warp-autonomous edge kernel over NSPLIT*256 quarter-bin segments.
// 32 edges/warp-iter, x pipelined via double-buffered warp-private smem.
__global__ void __launch_bounds__(256)
edge_mm_k(const float* __restrict__ x, const float* __restrict__ W,
          float* __restrict__ out) {
    const int seg = blockIdx.x & (NSPLIT - 1);
    const int w   = blockIdx.x >> 2;
    const int bs  = w * BIN_CAP + seg * SEG_CAP;
    const int be  = bs + g_bin_fill[seg * N_WEIGHTS + w];

    const int tid   = threadIdx.x;
    const int lane  = tid & 31;
    const int wid   = tid >> 5;
    const int qrt   = lane & 3;
    const int el    = lane >> 2;
    const int obase = qrt * 4;

    const float4* Wp = (const float4*)(W + (size_t)w * (D * D));
    unsigned long long wp0[D], wp1[D];
    {
        float4 r0[4], r1[4], r2[4], r3[4];
#pragma unroll
        for (int qq = 0; qq < 4; qq++) {
            r0[qq] = Wp[(obase + 0) * 4 + qq];
            r1[qq] = Wp[(obase + 1) * 4 + qq];
            r2[qq] = Wp[(obase + 2) * 4 + qq];
            r3[qq] = Wp[(obase + 3) * 4 + qq];
        }
#pragma unroll
        for (int qq = 0; qq < 4; qq++) {
            wp0[qq * 4 + 0] = pack2(r0[qq].x, r1[qq].x);
            wp0[qq * 4 + 1] = pack2(r0[qq].y, r1[qq].y);
            wp0[qq * 4 + 2] = pack2(r0[qq].z, r1[qq].z);
            wp0[qq * 4 + 3] = pack2(r0[qq].w, r1[qq].w);
            wp1[qq * 4 + 0] = pack2(r2[qq].x, r3[qq].x);
            wp1[qq * 4 + 1] = pack2(r2[qq].y, r3[qq].y);
            wp1[qq * 4 + 2] = pack2(r2[qq].z, r3[qq].z);
            wp1[qq * 4 + 3] = pack2(r2[qq].w, r3[qq].w);
        }
    }

    __shared__ float4 xs[8][2][32 * 5];

    const float4* x4 = (const float4*)x;
    const int gw   = wid;
    const int step = 8 * 32;

    int e0 = bs + gw * 32;
    if (e0 >= be) return;

    int2 uv0[4], uv1[4];
#pragma unroll
    for (int g = 0; g < 4; g++) {
        int e = e0 + g * 8 + el;
        uv0[g] = (e < be) ? g_suv[e] : make_int2(0, 0);
        int en = e + step;
        uv1[g] = (en < be) ? g_suv[en] : make_int2(0, 0);
    }

#pragma unroll
    for (int g = 0; g < 4; g++)
        xs[wid][0][(g * 8 + el) * 5 + qrt] = x4[(size_t)uv0[g].x * 4 + qrt];
    __syncwarp();

    int buf = 0;
    for (; e0 < be; e0 += step) {
        float4 xn[4];
#pragma unroll
        for (int g = 0; g < 4; g++)
            xn[g] = x4[(size_t)uv1[g].x * 4 + qrt];

        int2 uv2[4];
        const int e2 = e0 + 2 * step;
#pragma unroll
        for (int g = 0; g < 4; g++) {
            int e = e2 + g * 8 + el;
            uv2[g] = (e < be) ? g_suv[e] : make_int2(0, 0);
        }

        unsigned long long a0[4] = {0ull, 0ull, 0ull, 0ull};
        unsigned long long a1[4] = {0ull, 0ull, 0ull, 0ull};
#pragma unroll
        for (int q = 0; q < 4; q++) {
#pragma unroll
            for (int g = 0; g < 4; g++) {
                float4 xv = xs[wid][buf][(g * 8 + el) * 5 + q];
                unsigned long long b0 = pack2(xv.x, xv.x);
                unsigned long long b1 = pack2(xv.y, xv.y);
                unsigned long long b2 = pack2(xv.z, xv.z);
                unsigned long long b3 = pack2(xv.w, xv.w);
                fma2(a0[g], wp0[q * 4 + 0], b0);  fma2(a1[g], wp1[q * 4 + 0], b0);
                fma2(a0[g], wp0[q * 4 + 1], b1);  fma2(a1[g], wp1[q * 4 + 1], b1);
                fma2(a0[g], wp0[q * 4 + 2], b2);  fma2(a1[g], wp1[q * 4 + 2], b2);
                fma2(a0[g], wp0[q * 4 + 3], b3);  fma2(a1[g], wp1[q * 4 + 3], b3);
            }
        }

#pragma unroll
        for (int g = 0; g < 4; g++) {
            if (e0 + g * 8 + el < be) {
                float r0, r1, r2, r3;
                unpack2(a0[g], r0, r1);
                unpack2(a1[g], r2, r3);
                red_add_v4(out + (size_t)uv0[g].y * D + obase, r0, r1, r2, r3);
            }
        }

#pragma unroll
        for (int g = 0; g < 4; g++)
            xs[wid][buf ^ 1][(g * 8 + el) * 5 + qrt] = xn[g];
        __syncwarp();
        buf ^= 1;

#pragma unroll
        for (int g = 0; g < 4; g++) {
            uv0[g] = uv1[g];
            uv1[g] = uv2[g];
        }
    }
}

// relu: read accumulator -> write output; re-zero the segment counters.
__global__ void __launch_bounds__(256)
relu_k(float* __restrict__ out, int n4) {
    const float4* a4 = (const float4*)g_acc;
    float4* o4 = (float4*)out;
    int i = blockIdx.x * 512 + threadIdx.x;
#pragma unroll
    for (int rep = 0; rep < 2; rep++, i += 256) {
        if (i < n4) {
            float4 v = a4[i];
            v.x = fmaxf(v.x, 0.f);
            v.y = fmaxf(v.y, 0.f);
            v.z = fmaxf(v.z, 0.f);
            v.w = fmaxf(v.w, 0.f);
            o4[i] = v;
        }
    }
    if (blockIdx.x < NSPLIT)
        g_bin_fill[blockIdx.x * N_WEIGHTS + threadIdx.x] = 0;
}

// ---------------- launcher ----------------
extern "C" void kernel_launch(void* const* d_in, const int* in_sizes, int n_in,
                              void* d_out, int out_size) {
    const float* x    = (const float*)d_in[0];
    const float* W    = (const float*)d_in[1];
    const int*   u    = (const int*)d_in[2];
    const int*   v    = (const int*)d_in[3];
    const int*   widx = (const int*)d_in[4];
    float* out = (float*)d_out;

    const int E = in_sizes[2];

    float* acc;
    cudaGetSymbolAddress((void**)&acc, g_acc);

    scatter_k<<<(E + SC_CHUNK - 1) / SC_CHUNK, SC_THREADS>>>(u, v, widx, E);
    edge_mm_k<<<dim3(NSPLIT * N_WEIGHTS, 1), 256>>>(x, W, acc);
    int n4 = out_size / 4;
    relu_k<<<(n4 + 511) / 512, 256>>>(out, n4);
}